// round 1
// baseline (speedup 1.0000x reference)
#include <cuda_runtime.h>
#include <cstdint>

// Problem constants (fixed by the dataset)
#define NN 100000      // nodes
#define DD 64          // feature dim
#define EE 1250000     // edges
#define ND (NN * DD)   // 6.4M floats

// -------- scratch (device globals: allocation-free) --------
__device__ float g_deg[NN];
__device__ float g_dis[NN];
__device__ float g_wn[EE];
__device__ float g_buf1[ND];
__device__ float g_buf2[ND];

// -------- small elementwise kernels --------
__global__ void zero4_kernel(float4* p, int n4) {
    int i = blockIdx.x * blockDim.x + threadIdx.x;
    if (i < n4) p[i] = make_float4(0.f, 0.f, 0.f, 0.f);
}

__global__ void copy4_kernel(float4* dst, const float4* __restrict__ src, int n4) {
    int i = blockIdx.x * blockDim.x + threadIdx.x;
    if (i < n4) dst[i] = src[i];
}

__global__ void deg_accum_kernel(const int* __restrict__ row,
                                 const float* __restrict__ ew, int e) {
    int i = blockIdx.x * blockDim.x + threadIdx.x;
    if (i < e) atomicAdd(&g_deg[row[i]], ew[i]);
}

__global__ void dis_kernel(int n) {
    int i = blockIdx.x * blockDim.x + threadIdx.x;
    if (i < n) {
        float d = g_deg[i];
        g_dis[i] = (d > 0.f) ? rsqrtf(d) : 0.f;
    }
}

__global__ void wnorm_kernel(const int* __restrict__ row, const int* __restrict__ col,
                             const float* __restrict__ ew, int e) {
    int i = blockIdx.x * blockDim.x + threadIdx.x;
    if (i < e) g_wn[i] = g_dis[row[i]] * ew[i] * g_dis[col[i]];
}

// out = c0*x + c1*Lx + c2*LLx, coefficients derived from relu(temp) on device
__global__ void combine_kernel(const float4* __restrict__ x,
                               const float4* __restrict__ lx,
                               const float4* __restrict__ llx,
                               const float* __restrict__ temp,
                               float4* out, int n4) {
    int i = blockIdx.x * blockDim.x + threadIdx.x;
    if (i >= n4) return;
    float t0 = fmaxf(temp[0], 0.f);
    float t1 = fmaxf(temp[1], 0.f);
    float t2 = fmaxf(temp[2], 0.f);
    float c0 = t0;
    float c1 = t1 - t0;
    float c2 = (t0 + t2 - 2.f * t1) * 0.25f;
    float4 a = x[i], b = lx[i], c = llx[i];
    float4 o;
    o.x = c0 * a.x + c1 * b.x + c2 * c.x;
    o.y = c0 * a.y + c1 * b.y + c2 * c.y;
    o.z = c0 * a.z + c1 * b.z + c2 * c.z;
    o.w = c0 * a.w + c1 * b.w + c2 * c.w;
    out[i] = o;
}

// -------- SPMM: dst[row] += sign * w * src[col(.shuf)] --------
// 16 threads per edge, each handles a float4 (64 floats per row).
template <bool SUB, bool SHUF>
__global__ void spmm_kernel(const int* __restrict__ row,
                            const int* __restrict__ col,
                            const float* __restrict__ w,
                            const float* __restrict__ src,
                            float* dst,
                            const int* __restrict__ shuf,
                            int e) {
    int t = blockIdx.x * blockDim.x + threadIdx.x;
    int eid = t >> 4;
    if (eid >= e) return;
    int f = (t & 15) << 2;

    int r = __ldg(row + eid);
    int c = __ldg(col + eid);
    float wt = __ldg(w + eid);
    if (SHUF) c = __ldg(shuf + c);

    const float4 v = *reinterpret_cast<const float4*>(src + (size_t)c * DD + f);
    float s = SUB ? -wt : wt;
    float4 o;
    o.x = v.x * s; o.y = v.y * s; o.z = v.z * s; o.w = v.w * s;

    float* p = dst + (size_t)r * DD + f;
    asm volatile("red.global.add.v4.f32 [%0], {%1,%2,%3,%4};"
                 :: "l"(p), "f"(o.x), "f"(o.y), "f"(o.z), "f"(o.w)
                 : "memory");
}

extern "C" void kernel_launch(void* const* d_in, const int* in_sizes, int n_in,
                              void* d_out, int out_size) {
    const float* x    = (const float*)d_in[0];
    const int*   shuf = (const int*)  d_in[1];
    const int*   ei   = (const int*)  d_in[2];
    const float* ew   = (const float*)d_in[3];
    const int*   ni   = (const int*)  d_in[4];
    const float* nw   = (const float*)d_in[5];
    const float* temp = (const float*)d_in[6];
    float* out = (float*)d_out;          // [out | z_pos | z_neg], each N*D

    const int* erow = ei;
    const int* ecol = ei + EE;
    const int* nrow = ni;
    const int* ncol = ni + EE;

    float *p_deg, *p_wn, *p_buf1, *p_buf2;
    cudaGetSymbolAddress((void**)&p_deg,  g_deg);
    cudaGetSymbolAddress((void**)&p_wn,   g_wn);
    cudaGetSymbolAddress((void**)&p_buf1, g_buf1);
    cudaGetSymbolAddress((void**)&p_buf2, g_buf2);

    const int TB = 256;
    const int blkE    = (EE + TB - 1) / TB;            // per-edge kernels
    const int blkE16  = (EE * 16 + TB - 1) / TB;       // spmm kernels
    const int blkN    = (NN + TB - 1) / TB;
    const int blkND4  = (ND / 4 + TB - 1) / TB;
    const int blkN4   = (NN / 4 + TB - 1) / TB;

    // ---- normalized Laplacian weights ----
    zero4_kernel<<<blkN4, TB>>>((float4*)p_deg, NN / 4);
    deg_accum_kernel<<<blkE, TB>>>(erow, ew, EE);
    dis_kernel<<<blkN, TB>>>(NN);
    wnorm_kernel<<<blkE, TB>>>(erow, ecol, ew, EE);

    // ---- Lx = x - Anorm x ----
    copy4_kernel<<<blkND4, TB>>>((float4*)p_buf1, (const float4*)x, ND / 4);
    spmm_kernel<true, false><<<blkE16, TB>>>(erow, ecol, p_wn, x, p_buf1, nullptr, EE);

    // ---- LLx = Lx - Anorm Lx ----
    copy4_kernel<<<blkND4, TB>>>((float4*)p_buf2, (const float4*)p_buf1, ND / 4);
    spmm_kernel<true, false><<<blkE16, TB>>>(erow, ecol, p_wn, p_buf1, p_buf2, nullptr, EE);

    // ---- out = c0*x + c1*Lx + c2*LLx ----
    combine_kernel<<<blkND4, TB>>>((const float4*)x, (const float4*)p_buf1,
                                   (const float4*)p_buf2, temp, (float4*)out, ND / 4);

    // ---- zero accumulators (d_out is poisoned) ----
    zero4_kernel<<<blkND4, TB>>>((float4*)p_buf1, ND / 4);
    zero4_kernel<<<blkND4, TB>>>((float4*)p_buf2, ND / 4);
    zero4_kernel<<<2 * blkND4, TB>>>((float4*)(out + ND), 2 * ND / 4);

    // ---- z_pos = N(N(out)) ----
    spmm_kernel<false, false><<<blkE16, TB>>>(nrow, ncol, nw, out, p_buf1, nullptr, EE);
    spmm_kernel<false, false><<<blkE16, TB>>>(nrow, ncol, nw, p_buf1, out + ND, nullptr, EE);

    // ---- z_neg = N(N(out[shuf])) : fold permutation into first gather ----
    spmm_kernel<false, true><<<blkE16, TB>>>(nrow, ncol, nw, out, p_buf2, shuf, EE);
    spmm_kernel<false, false><<<blkE16, TB>>>(nrow, ncol, nw, p_buf2, out + 2 * ND, nullptr, EE);
}

// round 2
// speedup vs baseline: 2.0021x; 2.0021x over previous
#include <cuda_runtime.h>
#include <cstdint>

#define NN 100000      // nodes
#define DD 64          // feature dim
#define EE 1250000     // edges
#define ND (NN * DD)

// ---------------- scratch (device globals, allocation-free) ----------------
__device__ int   g_cnt0[NN];
__device__ int   g_cnt1[NN];
__device__ float g_degf[NN];
__device__ int   g_rowptr0[NN + 1];
__device__ int   g_rowptr1[NN + 1];
__device__ int   g_cur0[NN];
__device__ int   g_cur1[NN];
__device__ int   g_bsum0[128];
__device__ int   g_bsum1[128];
__device__ int2  g_edges0[EE];   // edge graph sorted by row: {col, w}
__device__ int2  g_edges1[EE];   // nb graph sorted by row:   {col, w}
__device__ int2  g_wne[EE];      // edge graph: {col, w_norm} (written by L1 pass)
__device__ float g_dis[NN];
__device__ float g_buf1[ND];
__device__ float g_buf2[ND];

// ---------------- CSR build ----------------
__global__ void zero_meta_kernel() {
    int i = blockIdx.x * blockDim.x + threadIdx.x;
    if (i < NN) { g_cnt0[i] = 0; g_cnt1[i] = 0; g_degf[i] = 0.f; }
}

__global__ void hist2_kernel(const int* __restrict__ er, const float* __restrict__ ew,
                             const int* __restrict__ nr) {
    int i = blockIdx.x * blockDim.x + threadIdx.x;
    if (i < EE) {
        int r = er[i];
        atomicAdd(&g_cnt0[r], 1);
        atomicAdd(&g_degf[r], ew[i]);
    } else if (i < 2 * EE) {
        atomicAdd(&g_cnt1[nr[i - EE]], 1);
    }
}

__global__ void dis_kernel() {
    int i = blockIdx.x * blockDim.x + threadIdx.x;
    if (i < NN) {
        float d = g_degf[i];
        g_dis[i] = (d > 0.f) ? rsqrtf(d) : 0.f;
    }
}

// scan phase 1: per-block exclusive scan of counts into rowptr; block totals to bsum
__global__ void scan1_kernel() {
    __shared__ int sh[1024];
    const int g = blockIdx.y;
    const int* cnt   = g ? g_cnt1    : g_cnt0;
    int*       rptr  = g ? g_rowptr1 : g_rowptr0;
    int*       bsum  = g ? g_bsum1   : g_bsum0;
    int tid = threadIdx.x;
    int i = blockIdx.x * 1024 + tid;
    int v = (i < NN) ? cnt[i] : 0;
    sh[tid] = v;
    __syncthreads();
    for (int off = 1; off < 1024; off <<= 1) {
        int t = (tid >= off) ? sh[tid - off] : 0;
        __syncthreads();
        sh[tid] += t;
        __syncthreads();
    }
    int incl = sh[tid];
    if (i < NN) rptr[i] = incl - v;                 // block-local exclusive
    if (tid == 1023) bsum[blockIdx.x] = incl;       // block total
}

// scan phase 2: exclusive scan of the (<=98) block sums
__global__ void scan2_kernel(int nblocks) {
    __shared__ int sh[128];
    const int g = blockIdx.y;
    int* bsum = g ? g_bsum1 : g_bsum0;
    int tid = threadIdx.x;
    int v = (tid < nblocks) ? bsum[tid] : 0;
    sh[tid] = v;
    __syncthreads();
    for (int off = 1; off < 128; off <<= 1) {
        int t = (tid >= off) ? sh[tid - off] : 0;
        __syncthreads();
        sh[tid] += t;
        __syncthreads();
    }
    if (tid < nblocks) bsum[tid] = sh[tid] - v;     // exclusive
}

// scan phase 3: add block offsets, init cursors, close rowptr
__global__ void scan3_kernel() {
    const int g = blockIdx.y;
    int* rptr = g ? g_rowptr1 : g_rowptr0;
    int* cur  = g ? g_cur1    : g_cur0;
    const int* bsum = g ? g_bsum1 : g_bsum0;
    int i = blockIdx.x * 1024 + threadIdx.x;
    if (i < NN) {
        int p = rptr[i] + bsum[blockIdx.x];
        rptr[i] = p;
        cur[i]  = p;
    }
    if (i == NN) rptr[NN] = EE;
}

__global__ void scatter2_kernel(const int* __restrict__ er, const int* __restrict__ ec,
                                const float* __restrict__ ew,
                                const int* __restrict__ nr, const int* __restrict__ nc,
                                const float* __restrict__ nw) {
    int i = blockIdx.x * blockDim.x + threadIdx.x;
    if (i < EE) {
        int p = atomicAdd(&g_cur0[er[i]], 1);
        g_edges0[p] = make_int2(ec[i], __float_as_int(ew[i]));
    } else if (i < 2 * EE) {
        int k = i - EE;
        int p = atomicAdd(&g_cur1[nr[k]], 1);
        g_edges1[p] = make_int2(nc[k], __float_as_int(nw[k]));
    }
}

// ---------------- CSR SPMM kernels (16 lanes per row, float4 per lane) ----------------

// buf1[r] = x[r] - sum_j wn_j * x[col_j]; also writes {col, wn} for pass 2.
__global__ void spmm_L1_kernel(const float* __restrict__ x) {
    int t = blockIdx.x * blockDim.x + threadIdx.x;
    int r = t >> 4;
    if (r >= NN) return;
    int f = (t & 15) << 2;
    int j   = g_rowptr0[r];
    int end = g_rowptr0[r + 1];
    float dr = g_dis[r];
    float4 acc = make_float4(0.f, 0.f, 0.f, 0.f);
    for (; j + 2 <= end; j += 2) {
        int2 e0 = g_edges0[j], e1 = g_edges0[j + 1];
        float w0 = dr * __int_as_float(e0.y) * __ldg(&g_dis[e0.x]);
        float w1 = dr * __int_as_float(e1.y) * __ldg(&g_dis[e1.x]);
        if (f == 0) {
            g_wne[j]     = make_int2(e0.x, __float_as_int(w0));
            g_wne[j + 1] = make_int2(e1.x, __float_as_int(w1));
        }
        float4 v0 = *(const float4*)(x + (size_t)e0.x * DD + f);
        float4 v1 = *(const float4*)(x + (size_t)e1.x * DD + f);
        acc.x += w0 * v0.x + w1 * v1.x;
        acc.y += w0 * v0.y + w1 * v1.y;
        acc.z += w0 * v0.z + w1 * v1.z;
        acc.w += w0 * v0.w + w1 * v1.w;
    }
    if (j < end) {
        int2 e0 = g_edges0[j];
        float w0 = dr * __int_as_float(e0.y) * __ldg(&g_dis[e0.x]);
        if (f == 0) g_wne[j] = make_int2(e0.x, __float_as_int(w0));
        float4 v0 = *(const float4*)(x + (size_t)e0.x * DD + f);
        acc.x += w0 * v0.x; acc.y += w0 * v0.y; acc.z += w0 * v0.z; acc.w += w0 * v0.w;
    }
    float4 xv = *(const float4*)(x + (size_t)r * DD + f);
    float4 o = make_float4(xv.x - acc.x, xv.y - acc.y, xv.z - acc.z, xv.w - acc.w);
    *(float4*)(g_buf1 + (size_t)r * DD + f) = o;
}

// out[r] = c0*x[r] + c1*Lx[r] + c2*(Lx[r] - sum_j wn_j * Lx[col_j])
__global__ void spmm_L2_kernel(const float* __restrict__ x,
                               const float* __restrict__ temp,
                               float* __restrict__ out) {
    int t = blockIdx.x * blockDim.x + threadIdx.x;
    int r = t >> 4;
    if (r >= NN) return;
    int f = (t & 15) << 2;
    int j   = g_rowptr0[r];
    int end = g_rowptr0[r + 1];
    float4 acc = make_float4(0.f, 0.f, 0.f, 0.f);
    for (; j + 2 <= end; j += 2) {
        int2 e0 = g_wne[j], e1 = g_wne[j + 1];
        float w0 = __int_as_float(e0.y), w1 = __int_as_float(e1.y);
        float4 v0 = *(const float4*)(g_buf1 + (size_t)e0.x * DD + f);
        float4 v1 = *(const float4*)(g_buf1 + (size_t)e1.x * DD + f);
        acc.x += w0 * v0.x + w1 * v1.x;
        acc.y += w0 * v0.y + w1 * v1.y;
        acc.z += w0 * v0.z + w1 * v1.z;
        acc.w += w0 * v0.w + w1 * v1.w;
    }
    if (j < end) {
        int2 e0 = g_wne[j];
        float w0 = __int_as_float(e0.y);
        float4 v0 = *(const float4*)(g_buf1 + (size_t)e0.x * DD + f);
        acc.x += w0 * v0.x; acc.y += w0 * v0.y; acc.z += w0 * v0.z; acc.w += w0 * v0.w;
    }
    float t0 = fmaxf(__ldg(temp + 0), 0.f);
    float t1 = fmaxf(__ldg(temp + 1), 0.f);
    float t2 = fmaxf(__ldg(temp + 2), 0.f);
    float c0 = t0;
    float c1 = t1 - t0;
    float c2 = (t0 + t2 - 2.f * t1) * 0.25f;
    float4 xv = *(const float4*)(x + (size_t)r * DD + f);
    float4 lx = *(const float4*)(g_buf1 + (size_t)r * DD + f);
    float4 o;
    o.x = c0 * xv.x + c1 * lx.x + c2 * (lx.x - acc.x);
    o.y = c0 * xv.y + c1 * lx.y + c2 * (lx.y - acc.y);
    o.z = c0 * xv.z + c1 * lx.z + c2 * (lx.z - acc.z);
    o.w = c0 * xv.w + c1 * lx.w + c2 * (lx.w - acc.w);
    *(float4*)(out + (size_t)r * DD + f) = o;
}

// dual first neighbor hop: buf1[r] = sum w*out[col]; buf2[r] = sum w*out[shuf[col]]
__global__ void spmm_N1_kernel(const float* __restrict__ out,
                               const int* __restrict__ shuf) {
    int t = blockIdx.x * blockDim.x + threadIdx.x;
    int r = t >> 4;
    if (r >= NN) return;
    int f = (t & 15) << 2;
    int j   = g_rowptr1[r];
    int end = g_rowptr1[r + 1];
    float4 ap = make_float4(0.f, 0.f, 0.f, 0.f);
    float4 an = make_float4(0.f, 0.f, 0.f, 0.f);
    for (; j < end; j++) {
        int2 e = g_edges1[j];
        int c = e.x;
        float w = __int_as_float(e.y);
        int sc = __ldg(shuf + c);
        float4 vp = *(const float4*)(out + (size_t)c  * DD + f);
        float4 vn = *(const float4*)(out + (size_t)sc * DD + f);
        ap.x += w * vp.x; ap.y += w * vp.y; ap.z += w * vp.z; ap.w += w * vp.w;
        an.x += w * vn.x; an.y += w * vn.y; an.z += w * vn.z; an.w += w * vn.w;
    }
    *(float4*)(g_buf1 + (size_t)r * DD + f) = ap;
    *(float4*)(g_buf2 + (size_t)r * DD + f) = an;
}

// dual second neighbor hop: zp[r] = sum w*buf1[col]; zn[r] = sum w*buf2[col]
__global__ void spmm_N2_kernel(float* __restrict__ zp, float* __restrict__ zn) {
    int t = blockIdx.x * blockDim.x + threadIdx.x;
    int r = t >> 4;
    if (r >= NN) return;
    int f = (t & 15) << 2;
    int j   = g_rowptr1[r];
    int end = g_rowptr1[r + 1];
    float4 ap = make_float4(0.f, 0.f, 0.f, 0.f);
    float4 an = make_float4(0.f, 0.f, 0.f, 0.f);
    for (; j < end; j++) {
        int2 e = g_edges1[j];
        int c = e.x;
        float w = __int_as_float(e.y);
        float4 vp = *(const float4*)(g_buf1 + (size_t)c * DD + f);
        float4 vn = *(const float4*)(g_buf2 + (size_t)c * DD + f);
        ap.x += w * vp.x; ap.y += w * vp.y; ap.z += w * vp.z; ap.w += w * vp.w;
        an.x += w * vn.x; an.y += w * vn.y; an.z += w * vn.z; an.w += w * vn.w;
    }
    *(float4*)(zp + (size_t)r * DD + f) = ap;
    *(float4*)(zn + (size_t)r * DD + f) = an;
}

extern "C" void kernel_launch(void* const* d_in, const int* in_sizes, int n_in,
                              void* d_out, int out_size) {
    const float* x    = (const float*)d_in[0];
    const int*   shuf = (const int*)  d_in[1];
    const int*   ei   = (const int*)  d_in[2];
    const float* ew   = (const float*)d_in[3];
    const int*   ni   = (const int*)  d_in[4];
    const float* nw   = (const float*)d_in[5];
    const float* temp = (const float*)d_in[6];
    float* out = (float*)d_out;   // [out | z_pos | z_neg]

    const int* erow = ei;
    const int* ecol = ei + EE;
    const int* nrow = ni;
    const int* ncol = ni + EE;

    const int TB = 256;
    const int blkN   = (NN + TB - 1) / TB;
    const int blk2E  = (2 * EE + TB - 1) / TB;
    const int blkR16 = (NN * 16 + TB - 1) / TB;
    const int nScanB = (NN + 1023) / 1024;   // 98

    // ---- CSR build for both graphs + weighted degree ----
    zero_meta_kernel<<<blkN, TB>>>();
    hist2_kernel<<<blk2E, TB>>>(erow, ew, nrow);
    dis_kernel<<<blkN, TB>>>();
    scan1_kernel<<<dim3(nScanB, 2), 1024>>>();
    scan2_kernel<<<dim3(1, 2), 128>>>(nScanB);
    scan3_kernel<<<dim3(nScanB, 2), 1024>>>();
    scatter2_kernel<<<blk2E, TB>>>(erow, ecol, ew, nrow, ncol, nw);

    // ---- spectral polynomial: out = c0*x + c1*Lx + c2*LLx ----
    spmm_L1_kernel<<<blkR16, TB>>>(x);
    spmm_L2_kernel<<<blkR16, TB>>>(x, temp, out);

    // ---- z_pos = N(N(out)), z_neg = N(N(out[shuf])) ----
    spmm_N1_kernel<<<blkR16, TB>>>(out, shuf);
    spmm_N2_kernel<<<blkR16, TB>>>(out + (size_t)ND, out + 2 * (size_t)ND);
}

// round 3
// speedup vs baseline: 2.1771x; 1.0874x over previous
#include <cuda_runtime.h>
#include <cuda_fp16.h>
#include <cstdint>

#define NN 100000      // nodes
#define DD 64          // feature dim
#define EE 1250000     // edges
#define ND (NN * DD)
#define NH (ND / 8)    // uint4 count for fp16 feature arrays (8 halfs per uint4)

// ---------------- scratch (device globals, allocation-free) ----------------
__device__ int   g_cnt0[NN];
__device__ int   g_cnt1[NN];
__device__ float g_degf[NN];
__device__ int   g_rowptr0[NN + 1];
__device__ int   g_rowptr1[NN + 1];
__device__ int   g_cur0[NN];
__device__ int   g_cur1[NN];
__device__ int   g_bsum0[128];
__device__ int   g_bsum1[128];
__device__ int2  g_edges0[EE];   // edge graph sorted by row: {col, w}
__device__ int2  g_edges1[EE];   // nb graph sorted by row:   {col, w}
__device__ int2  g_wne[EE];      // edge graph: {col, w_norm}
__device__ float g_dis[NN];
__device__ float g_buf1[ND];     // Lx fp32
__device__ uint4 g_xh[NH];       // x fp16
__device__ uint4 g_lxh[NH];      // Lx fp16
__device__ uint4 g_outh[NH];     // out fp16
__device__ uint4 g_outsh[NH];    // out[shuf] fp16
__device__ uint4 g_b1h[NH];      // N(out) fp16
__device__ uint4 g_b2h[NH];      // N(out[shuf]) fp16

// ---------------- helpers ----------------
__device__ __forceinline__ void fma8(float* acc, uint4 v, float w) {
    __half2* h = (__half2*)&v;
#pragma unroll
    for (int k = 0; k < 4; k++) {
        float2 f = __half22float2(h[k]);
        acc[2 * k]     += w * f.x;
        acc[2 * k + 1] += w * f.y;
    }
}

__device__ __forceinline__ uint4 pack8(const float* o) {
    uint4 u;
    __half2 h0 = __floats2half2_rn(o[0], o[1]);
    __half2 h1 = __floats2half2_rn(o[2], o[3]);
    __half2 h2 = __floats2half2_rn(o[4], o[5]);
    __half2 h3 = __floats2half2_rn(o[6], o[7]);
    u.x = *reinterpret_cast<unsigned*>(&h0);
    u.y = *reinterpret_cast<unsigned*>(&h1);
    u.z = *reinterpret_cast<unsigned*>(&h2);
    u.w = *reinterpret_cast<unsigned*>(&h3);
    return u;
}

// ---------------- CSR build ----------------
__global__ void zero_meta_kernel() {
    int i = blockIdx.x * blockDim.x + threadIdx.x;
    if (i < NN) { g_cnt0[i] = 0; g_cnt1[i] = 0; g_degf[i] = 0.f; }
}

__global__ void hist2_kernel(const int* __restrict__ er, const float* __restrict__ ew,
                             const int* __restrict__ nr) {
    int i = blockIdx.x * blockDim.x + threadIdx.x;
    if (i < EE) {
        int r = er[i];
        atomicAdd(&g_cnt0[r], 1);
        atomicAdd(&g_degf[r], ew[i]);
    } else if (i < 2 * EE) {
        atomicAdd(&g_cnt1[nr[i - EE]], 1);
    }
}

__global__ void dis_kernel() {
    int i = blockIdx.x * blockDim.x + threadIdx.x;
    if (i < NN) {
        float d = g_degf[i];
        g_dis[i] = (d > 0.f) ? rsqrtf(d) : 0.f;
    }
}

__global__ void scan1_kernel() {
    __shared__ int sh[1024];
    const int g = blockIdx.y;
    const int* cnt  = g ? g_cnt1    : g_cnt0;
    int*       rptr = g ? g_rowptr1 : g_rowptr0;
    int*       bsum = g ? g_bsum1   : g_bsum0;
    int tid = threadIdx.x;
    int i = blockIdx.x * 1024 + tid;
    int v = (i < NN) ? cnt[i] : 0;
    sh[tid] = v;
    __syncthreads();
    for (int off = 1; off < 1024; off <<= 1) {
        int t = (tid >= off) ? sh[tid - off] : 0;
        __syncthreads();
        sh[tid] += t;
        __syncthreads();
    }
    int incl = sh[tid];
    if (i < NN) rptr[i] = incl - v;
    if (tid == 1023) bsum[blockIdx.x] = incl;
}

__global__ void scan2_kernel(int nblocks) {
    __shared__ int sh[128];
    const int g = blockIdx.y;
    int* bsum = g ? g_bsum1 : g_bsum0;
    int tid = threadIdx.x;
    int v = (tid < nblocks) ? bsum[tid] : 0;
    sh[tid] = v;
    __syncthreads();
    for (int off = 1; off < 128; off <<= 1) {
        int t = (tid >= off) ? sh[tid - off] : 0;
        __syncthreads();
        sh[tid] += t;
        __syncthreads();
    }
    if (tid < nblocks) bsum[tid] = sh[tid] - v;
}

__global__ void scan3_kernel() {
    const int g = blockIdx.y;
    int* rptr = g ? g_rowptr1 : g_rowptr0;
    int* cur  = g ? g_cur1    : g_cur0;
    const int* bsum = g ? g_bsum1 : g_bsum0;
    int i = blockIdx.x * 1024 + threadIdx.x;
    if (i < NN) {
        int p = rptr[i] + bsum[blockIdx.x];
        rptr[i] = p;
        cur[i]  = p;
    }
    if (i == NN) rptr[NN] = EE;
}

__global__ void scatter2_kernel(const int* __restrict__ er, const int* __restrict__ ec,
                                const float* __restrict__ ew,
                                const int* __restrict__ nr, const int* __restrict__ nc,
                                const float* __restrict__ nw) {
    int i = blockIdx.x * blockDim.x + threadIdx.x;
    if (i < EE) {
        int p = atomicAdd(&g_cur0[er[i]], 1);
        g_edges0[p] = make_int2(ec[i], __float_as_int(ew[i]));
    } else if (i < 2 * EE) {
        int k = i - EE;
        int p = atomicAdd(&g_cur1[nr[k]], 1);
        g_edges1[p] = make_int2(nc[k], __float_as_int(nw[k]));
    }
}

// ---------------- fp16 copy of x ----------------
__global__ void xh_kernel(const float* __restrict__ x) {
    int i = blockIdx.x * blockDim.x + threadIdx.x;   // one uint4 (8 floats) each
    if (i >= NH) return;
    const float* p = x + (size_t)i * 8;
    float o[8];
#pragma unroll
    for (int k = 0; k < 8; k++) o[k] = p[k];
    g_xh[i] = pack8(o);
}

// ---------------- SPMM kernels: 8 lanes per row, 8 features per lane ----------------

// Lx = x - Anorm x (gathers xh fp16); writes buf1 fp32, lxh fp16, and wne
__global__ void spmm_L1_kernel(const float* __restrict__ x) {
    int t = blockIdx.x * blockDim.x + threadIdx.x;
    int r = t >> 3;
    if (r >= NN) return;
    int lane = t & 7;
    int f = lane << 3;
    int j   = g_rowptr0[r];
    int end = g_rowptr0[r + 1];
    float dr = g_dis[r];
    float acc[8] = {0.f, 0.f, 0.f, 0.f, 0.f, 0.f, 0.f, 0.f};
    for (; j + 2 <= end; j += 2) {
        int2 e0 = g_edges0[j], e1 = g_edges0[j + 1];
        float w0 = dr * __int_as_float(e0.y) * __ldg(&g_dis[e0.x]);
        float w1 = dr * __int_as_float(e1.y) * __ldg(&g_dis[e1.x]);
        if (lane == 0) {
            g_wne[j]     = make_int2(e0.x, __float_as_int(w0));
            g_wne[j + 1] = make_int2(e1.x, __float_as_int(w1));
        }
        uint4 v0 = g_xh[(size_t)e0.x * 8 + lane];
        uint4 v1 = g_xh[(size_t)e1.x * 8 + lane];
        fma8(acc, v0, w0);
        fma8(acc, v1, w1);
    }
    if (j < end) {
        int2 e0 = g_edges0[j];
        float w0 = dr * __int_as_float(e0.y) * __ldg(&g_dis[e0.x]);
        if (lane == 0) g_wne[j] = make_int2(e0.x, __float_as_int(w0));
        uint4 v0 = g_xh[(size_t)e0.x * 8 + lane];
        fma8(acc, v0, w0);
    }
    float4 xa = *(const float4*)(x + (size_t)r * DD + f);
    float4 xb = *(const float4*)(x + (size_t)r * DD + f + 4);
    float o[8];
    o[0] = xa.x - acc[0]; o[1] = xa.y - acc[1]; o[2] = xa.z - acc[2]; o[3] = xa.w - acc[3];
    o[4] = xb.x - acc[4]; o[5] = xb.y - acc[5]; o[6] = xb.z - acc[6]; o[7] = xb.w - acc[7];
    float* bp = g_buf1 + (size_t)r * DD + f;
    *(float4*)(bp)     = make_float4(o[0], o[1], o[2], o[3]);
    *(float4*)(bp + 4) = make_float4(o[4], o[5], o[6], o[7]);
    g_lxh[(size_t)r * 8 + lane] = pack8(o);
}

// out = c0*x + c1*Lx + c2*(Lx - Anorm*Lx)  (gathers lxh fp16); writes out fp32 + outh fp16
__global__ void spmm_L2_kernel(const float* __restrict__ x,
                               const float* __restrict__ temp,
                               float* __restrict__ out) {
    int t = blockIdx.x * blockDim.x + threadIdx.x;
    int r = t >> 3;
    if (r >= NN) return;
    int lane = t & 7;
    int f = lane << 3;
    int j   = g_rowptr0[r];
    int end = g_rowptr0[r + 1];
    float acc[8] = {0.f, 0.f, 0.f, 0.f, 0.f, 0.f, 0.f, 0.f};
    for (; j + 2 <= end; j += 2) {
        int2 e0 = g_wne[j], e1 = g_wne[j + 1];
        float w0 = __int_as_float(e0.y), w1 = __int_as_float(e1.y);
        uint4 v0 = g_lxh[(size_t)e0.x * 8 + lane];
        uint4 v1 = g_lxh[(size_t)e1.x * 8 + lane];
        fma8(acc, v0, w0);
        fma8(acc, v1, w1);
    }
    if (j < end) {
        int2 e0 = g_wne[j];
        uint4 v0 = g_lxh[(size_t)e0.x * 8 + lane];
        fma8(acc, v0, __int_as_float(e0.y));
    }
    float t0 = fmaxf(__ldg(temp + 0), 0.f);
    float t1 = fmaxf(__ldg(temp + 1), 0.f);
    float t2 = fmaxf(__ldg(temp + 2), 0.f);
    float c0 = t0;
    float c1 = t1 - t0;
    float c2 = (t0 + t2 - 2.f * t1) * 0.25f;
    float4 xa = *(const float4*)(x + (size_t)r * DD + f);
    float4 xb = *(const float4*)(x + (size_t)r * DD + f + 4);
    const float* lp = g_buf1 + (size_t)r * DD + f;
    float4 la = *(const float4*)(lp);
    float4 lb = *(const float4*)(lp + 4);
    float o[8];
    o[0] = c0 * xa.x + c1 * la.x + c2 * (la.x - acc[0]);
    o[1] = c0 * xa.y + c1 * la.y + c2 * (la.y - acc[1]);
    o[2] = c0 * xa.z + c1 * la.z + c2 * (la.z - acc[2]);
    o[3] = c0 * xa.w + c1 * la.w + c2 * (la.w - acc[3]);
    o[4] = c0 * xb.x + c1 * lb.x + c2 * (lb.x - acc[4]);
    o[5] = c0 * xb.y + c1 * lb.y + c2 * (lb.y - acc[5]);
    o[6] = c0 * xb.z + c1 * lb.z + c2 * (lb.z - acc[6]);
    o[7] = c0 * xb.w + c1 * lb.w + c2 * (lb.w - acc[7]);
    float* op = out + (size_t)r * DD + f;
    *(float4*)(op)     = make_float4(o[0], o[1], o[2], o[3]);
    *(float4*)(op + 4) = make_float4(o[4], o[5], o[6], o[7]);
    g_outh[(size_t)r * 8 + lane] = pack8(o);
}

// materialize out[shuf] in fp16: outsh[i] = outh[shuf[i]]
__global__ void outsh_kernel(const int* __restrict__ shuf) {
    int t = blockIdx.x * blockDim.x + threadIdx.x;
    int i = t >> 3;
    if (i >= NN) return;
    int lane = t & 7;
    int s = __ldg(shuf + i);
    g_outsh[(size_t)i * 8 + lane] = g_outh[(size_t)s * 8 + lane];
}

// dual hop 1: b1h[r] = sum w*outh[col]; b2h[r] = sum w*outsh[col]
__global__ void spmm_N1_kernel() {
    int t = blockIdx.x * blockDim.x + threadIdx.x;
    int r = t >> 3;
    if (r >= NN) return;
    int lane = t & 7;
    int j   = g_rowptr1[r];
    int end = g_rowptr1[r + 1];
    float ap[8] = {0.f, 0.f, 0.f, 0.f, 0.f, 0.f, 0.f, 0.f};
    float an[8] = {0.f, 0.f, 0.f, 0.f, 0.f, 0.f, 0.f, 0.f};
    for (; j < end; j++) {
        int2 e = g_edges1[j];
        float w = __int_as_float(e.y);
        uint4 vp = g_outh[(size_t)e.x * 8 + lane];
        uint4 vn = g_outsh[(size_t)e.x * 8 + lane];
        fma8(ap, vp, w);
        fma8(an, vn, w);
    }
    g_b1h[(size_t)r * 8 + lane] = pack8(ap);
    g_b2h[(size_t)r * 8 + lane] = pack8(an);
}

// dual hop 2: zp[r] = sum w*b1h[col]; zn[r] = sum w*b2h[col]  (fp32 out)
__global__ void spmm_N2_kernel(float* __restrict__ zp, float* __restrict__ zn) {
    int t = blockIdx.x * blockDim.x + threadIdx.x;
    int r = t >> 3;
    if (r >= NN) return;
    int lane = t & 7;
    int f = lane << 3;
    int j   = g_rowptr1[r];
    int end = g_rowptr1[r + 1];
    float ap[8] = {0.f, 0.f, 0.f, 0.f, 0.f, 0.f, 0.f, 0.f};
    float an[8] = {0.f, 0.f, 0.f, 0.f, 0.f, 0.f, 0.f, 0.f};
    for (; j < end; j++) {
        int2 e = g_edges1[j];
        float w = __int_as_float(e.y);
        uint4 vp = g_b1h[(size_t)e.x * 8 + lane];
        uint4 vn = g_b2h[(size_t)e.x * 8 + lane];
        fma8(ap, vp, w);
        fma8(an, vn, w);
    }
    float* pp = zp + (size_t)r * DD + f;
    float* pn = zn + (size_t)r * DD + f;
    *(float4*)(pp)     = make_float4(ap[0], ap[1], ap[2], ap[3]);
    *(float4*)(pp + 4) = make_float4(ap[4], ap[5], ap[6], ap[7]);
    *(float4*)(pn)     = make_float4(an[0], an[1], an[2], an[3]);
    *(float4*)(pn + 4) = make_float4(an[4], an[5], an[6], an[7]);
}

extern "C" void kernel_launch(void* const* d_in, const int* in_sizes, int n_in,
                              void* d_out, int out_size) {
    const float* x    = (const float*)d_in[0];
    const int*   shuf = (const int*)  d_in[1];
    const int*   ei   = (const int*)  d_in[2];
    const float* ew   = (const float*)d_in[3];
    const int*   ni   = (const int*)  d_in[4];
    const float* nw   = (const float*)d_in[5];
    const float* temp = (const float*)d_in[6];
    float* out = (float*)d_out;   // [out | z_pos | z_neg]

    const int* erow = ei;
    const int* ecol = ei + EE;
    const int* nrow = ni;
    const int* ncol = ni + EE;

    const int TB = 256;
    const int blkN   = (NN + TB - 1) / TB;
    const int blk2E  = (2 * EE + TB - 1) / TB;
    const int blkR8  = (NN * 8 + TB - 1) / TB;
    const int blkNH  = (NH + TB - 1) / TB;
    const int nScanB = (NN + 1023) / 1024;

    // ---- CSR build (both graphs) + weighted degree + fp16 x ----
    zero_meta_kernel<<<blkN, TB>>>();
    hist2_kernel<<<blk2E, TB>>>(erow, ew, nrow);
    xh_kernel<<<blkNH, TB>>>(x);
    dis_kernel<<<blkN, TB>>>();
    scan1_kernel<<<dim3(nScanB, 2), 1024>>>();
    scan2_kernel<<<dim3(1, 2), 128>>>(nScanB);
    scan3_kernel<<<dim3(nScanB, 2), 1024>>>();
    scatter2_kernel<<<blk2E, TB>>>(erow, ecol, ew, nrow, ncol, nw);

    // ---- spectral polynomial ----
    spmm_L1_kernel<<<blkR8, TB>>>(x);
    spmm_L2_kernel<<<blkR8, TB>>>(x, temp, out);

    // ---- z_pos / z_neg ----
    outsh_kernel<<<blkR8, TB>>>(shuf);
    spmm_N1_kernel<<<blkR8, TB>>>();
    spmm_N2_kernel<<<blkR8, TB>>>(out + (size_t)ND, out + 2 * (size_t)ND);
}

// round 4
// speedup vs baseline: 2.2591x; 1.0377x over previous
#include <cuda_runtime.h>
#include <cuda_fp16.h>
#include <cstdint>

#define NN 100000      // nodes
#define DD 64          // feature dim
#define EE 1250000     // edges
#define ND (NN * DD)
#define NH2 (ND / 4)   // uint2 count for fp16 feature arrays (4 halfs per uint2)

// ---------------- scratch (device globals, allocation-free) ----------------
__device__ int   g_cnt0[NN];
__device__ int   g_cnt1[NN];
__device__ float g_degf[NN];
__device__ int   g_rowptr0[NN + 1];
__device__ int   g_rowptr1[NN + 1];
__device__ int   g_cur0[NN];
__device__ int   g_cur1[NN];
__device__ int   g_bsum0[128];
__device__ int   g_bsum1[128];
__device__ int2  g_edges0[EE];   // edge graph sorted by row: {col, w}
__device__ int2  g_edges1[EE];   // nb graph sorted by row:   {col, w}
__device__ int2  g_wne[EE];      // edge graph: {col, w_norm}
__device__ float g_dis[NN];
__device__ float g_buf1[ND];     // Lx fp32
__device__ uint2 g_xh[NH2];      // x fp16
__device__ uint2 g_lxh[NH2];     // Lx fp16
__device__ uint2 g_outh[NH2];    // out fp16
__device__ uint2 g_outsh[NH2];   // out[shuf] fp16
__device__ uint2 g_b1h[NH2];     // N(out) fp16
__device__ uint2 g_b2h[NH2];     // N(out[shuf]) fp16

// ---------------- helpers ----------------
__device__ __forceinline__ void fma4(float* acc, uint2 v, float w) {
    __half2 h0 = *reinterpret_cast<__half2*>(&v.x);
    __half2 h1 = *reinterpret_cast<__half2*>(&v.y);
    float2 f0 = __half22float2(h0);
    float2 f1 = __half22float2(h1);
    acc[0] += w * f0.x;
    acc[1] += w * f0.y;
    acc[2] += w * f1.x;
    acc[3] += w * f1.y;
}

__device__ __forceinline__ uint2 pack4(float a, float b, float c, float d) {
    uint2 u;
    __half2 h0 = __floats2half2_rn(a, b);
    __half2 h1 = __floats2half2_rn(c, d);
    u.x = *reinterpret_cast<unsigned*>(&h0);
    u.y = *reinterpret_cast<unsigned*>(&h1);
    return u;
}

// ---------------- CSR build ----------------
__global__ void zero_meta_kernel() {
    int i = blockIdx.x * blockDim.x + threadIdx.x;
    if (i < NN) { g_cnt0[i] = 0; g_cnt1[i] = 0; g_degf[i] = 0.f; }
}

// segment 1: edge-graph histogram + weighted degree; segment 2: nb histogram;
// segment 3: fp16 copy of x (4 floats per thread)
__global__ void hist2_xh_kernel(const int* __restrict__ er, const float* __restrict__ ew,
                                const int* __restrict__ nr, const float* __restrict__ x) {
    int i = blockIdx.x * blockDim.x + threadIdx.x;
    if (i < EE) {
        int r = er[i];
        atomicAdd(&g_cnt0[r], 1);
        atomicAdd(&g_degf[r], ew[i]);
    } else if (i < 2 * EE) {
        atomicAdd(&g_cnt1[nr[i - EE]], 1);
    } else if (i < 2 * EE + NH2) {
        int k = i - 2 * EE;
        float4 v = *(const float4*)(x + (size_t)k * 4);
        g_xh[k] = pack4(v.x, v.y, v.z, v.w);
    }
}

// scan phase 1 (+ fused dis computation)
__global__ void scan1_kernel() {
    __shared__ int sh[1024];
    const int g = blockIdx.y;
    const int* cnt  = g ? g_cnt1    : g_cnt0;
    int*       rptr = g ? g_rowptr1 : g_rowptr0;
    int*       bsum = g ? g_bsum1   : g_bsum0;
    int tid = threadIdx.x;
    int i = blockIdx.x * 1024 + tid;
    if (g == 0 && i < NN) {
        float d = g_degf[i];
        g_dis[i] = (d > 0.f) ? rsqrtf(d) : 0.f;
    }
    int v = (i < NN) ? cnt[i] : 0;
    sh[tid] = v;
    __syncthreads();
    for (int off = 1; off < 1024; off <<= 1) {
        int t = (tid >= off) ? sh[tid - off] : 0;
        __syncthreads();
        sh[tid] += t;
        __syncthreads();
    }
    int incl = sh[tid];
    if (i < NN) rptr[i] = incl - v;
    if (tid == 1023) bsum[blockIdx.x] = incl;
}

__global__ void scan2_kernel(int nblocks) {
    __shared__ int sh[128];
    const int g = blockIdx.y;
    int* bsum = g ? g_bsum1 : g_bsum0;
    int tid = threadIdx.x;
    int v = (tid < nblocks) ? bsum[tid] : 0;
    sh[tid] = v;
    __syncthreads();
    for (int off = 1; off < 128; off <<= 1) {
        int t = (tid >= off) ? sh[tid - off] : 0;
        __syncthreads();
        sh[tid] += t;
        __syncthreads();
    }
    if (tid < nblocks) bsum[tid] = sh[tid] - v;
}

__global__ void scan3_kernel() {
    const int g = blockIdx.y;
    int* rptr = g ? g_rowptr1 : g_rowptr0;
    int* cur  = g ? g_cur1    : g_cur0;
    const int* bsum = g ? g_bsum1 : g_bsum0;
    int i = blockIdx.x * 1024 + threadIdx.x;
    if (i < NN) {
        int p = rptr[i] + bsum[blockIdx.x];
        rptr[i] = p;
        cur[i]  = p;
    }
    if (i == NN) rptr[NN] = EE;
}

__global__ void scatter2_kernel(const int* __restrict__ er, const int* __restrict__ ec,
                                const float* __restrict__ ew,
                                const int* __restrict__ nr, const int* __restrict__ nc,
                                const float* __restrict__ nw) {
    int i = blockIdx.x * blockDim.x + threadIdx.x;
    if (i < EE) {
        int p = atomicAdd(&g_cur0[er[i]], 1);
        g_edges0[p] = make_int2(ec[i], __float_as_int(ew[i]));
    } else if (i < 2 * EE) {
        int k = i - EE;
        int p = atomicAdd(&g_cur1[nr[k]], 1);
        g_edges1[p] = make_int2(nc[k], __float_as_int(nw[k]));
    }
}

// ---------------- SPMM kernels: 16 lanes per row, 4 features per lane ----------------

// Lx = x - Anorm x (gathers xh fp16); writes buf1 fp32, lxh fp16, and wne
__global__ void spmm_L1_kernel(const float* __restrict__ x) {
    int t = blockIdx.x * blockDim.x + threadIdx.x;
    int r = t >> 4;
    if (r >= NN) return;
    int lane = t & 15;
    int f = lane << 2;
    int j   = g_rowptr0[r];
    int end = g_rowptr0[r + 1];
    float dr = g_dis[r];
    float acc[4] = {0.f, 0.f, 0.f, 0.f};
    for (; j + 2 <= end; j += 2) {
        int2 e0 = g_edges0[j], e1 = g_edges0[j + 1];
        float d0 = __ldg(&g_dis[e0.x]);
        float d1 = __ldg(&g_dis[e1.x]);
        uint2 v0 = g_xh[(size_t)e0.x * 16 + lane];
        uint2 v1 = g_xh[(size_t)e1.x * 16 + lane];
        float w0 = dr * __int_as_float(e0.y) * d0;
        float w1 = dr * __int_as_float(e1.y) * d1;
        if (lane == 0) {
            g_wne[j]     = make_int2(e0.x, __float_as_int(w0));
            g_wne[j + 1] = make_int2(e1.x, __float_as_int(w1));
        }
        fma4(acc, v0, w0);
        fma4(acc, v1, w1);
    }
    if (j < end) {
        int2 e0 = g_edges0[j];
        float w0 = dr * __int_as_float(e0.y) * __ldg(&g_dis[e0.x]);
        if (lane == 0) g_wne[j] = make_int2(e0.x, __float_as_int(w0));
        uint2 v0 = g_xh[(size_t)e0.x * 16 + lane];
        fma4(acc, v0, w0);
    }
    float4 xv = *(const float4*)(x + (size_t)r * DD + f);
    float o0 = xv.x - acc[0], o1 = xv.y - acc[1], o2 = xv.z - acc[2], o3 = xv.w - acc[3];
    *(float4*)(g_buf1 + (size_t)r * DD + f) = make_float4(o0, o1, o2, o3);
    g_lxh[(size_t)r * 16 + lane] = pack4(o0, o1, o2, o3);
}

// out = c0*x + c1*Lx + c2*(Lx - Anorm*Lx); writes out fp32 + outh fp16
__global__ void spmm_L2_kernel(const float* __restrict__ x,
                               const float* __restrict__ temp,
                               float* __restrict__ out) {
    int t = blockIdx.x * blockDim.x + threadIdx.x;
    int r = t >> 4;
    if (r >= NN) return;
    int lane = t & 15;
    int f = lane << 2;
    int j   = g_rowptr0[r];
    int end = g_rowptr0[r + 1];
    float acc[4] = {0.f, 0.f, 0.f, 0.f};
    for (; j + 2 <= end; j += 2) {
        int2 e0 = g_wne[j], e1 = g_wne[j + 1];
        uint2 v0 = g_lxh[(size_t)e0.x * 16 + lane];
        uint2 v1 = g_lxh[(size_t)e1.x * 16 + lane];
        fma4(acc, v0, __int_as_float(e0.y));
        fma4(acc, v1, __int_as_float(e1.y));
    }
    if (j < end) {
        int2 e0 = g_wne[j];
        uint2 v0 = g_lxh[(size_t)e0.x * 16 + lane];
        fma4(acc, v0, __int_as_float(e0.y));
    }
    float t0 = fmaxf(__ldg(temp + 0), 0.f);
    float t1 = fmaxf(__ldg(temp + 1), 0.f);
    float t2 = fmaxf(__ldg(temp + 2), 0.f);
    float c0 = t0;
    float c1 = t1 - t0;
    float c2 = (t0 + t2 - 2.f * t1) * 0.25f;
    float4 xv = *(const float4*)(x + (size_t)r * DD + f);
    float4 lv = *(const float4*)(g_buf1 + (size_t)r * DD + f);
    float o0 = c0 * xv.x + c1 * lv.x + c2 * (lv.x - acc[0]);
    float o1 = c0 * xv.y + c1 * lv.y + c2 * (lv.y - acc[1]);
    float o2 = c0 * xv.z + c1 * lv.z + c2 * (lv.z - acc[2]);
    float o3 = c0 * xv.w + c1 * lv.w + c2 * (lv.w - acc[3]);
    *(float4*)(out + (size_t)r * DD + f) = make_float4(o0, o1, o2, o3);
    g_outh[(size_t)r * 16 + lane] = pack4(o0, o1, o2, o3);
}

// materialize out[shuf] fp16
__global__ void outsh_kernel(const int* __restrict__ shuf) {
    int t = blockIdx.x * blockDim.x + threadIdx.x;
    int i = t >> 4;
    if (i >= NN) return;
    int lane = t & 15;
    int s = __ldg(shuf + i);
    g_outsh[(size_t)i * 16 + lane] = g_outh[(size_t)s * 16 + lane];
}

// dual hop 1: b1h[r] = sum w*outh[col]; b2h[r] = sum w*outsh[col]
__global__ void spmm_N1_kernel() {
    int t = blockIdx.x * blockDim.x + threadIdx.x;
    int r = t >> 4;
    if (r >= NN) return;
    int lane = t & 15;
    int j   = g_rowptr1[r];
    int end = g_rowptr1[r + 1];
    float ap[4] = {0.f, 0.f, 0.f, 0.f};
    float an[4] = {0.f, 0.f, 0.f, 0.f};
    for (; j + 2 <= end; j += 2) {
        int2 e0 = g_edges1[j], e1 = g_edges1[j + 1];
        float w0 = __int_as_float(e0.y), w1 = __int_as_float(e1.y);
        uint2 vp0 = g_outh [(size_t)e0.x * 16 + lane];
        uint2 vn0 = g_outsh[(size_t)e0.x * 16 + lane];
        uint2 vp1 = g_outh [(size_t)e1.x * 16 + lane];
        uint2 vn1 = g_outsh[(size_t)e1.x * 16 + lane];
        fma4(ap, vp0, w0);
        fma4(an, vn0, w0);
        fma4(ap, vp1, w1);
        fma4(an, vn1, w1);
    }
    if (j < end) {
        int2 e0 = g_edges1[j];
        float w0 = __int_as_float(e0.y);
        uint2 vp0 = g_outh [(size_t)e0.x * 16 + lane];
        uint2 vn0 = g_outsh[(size_t)e0.x * 16 + lane];
        fma4(ap, vp0, w0);
        fma4(an, vn0, w0);
    }
    g_b1h[(size_t)r * 16 + lane] = pack4(ap[0], ap[1], ap[2], ap[3]);
    g_b2h[(size_t)r * 16 + lane] = pack4(an[0], an[1], an[2], an[3]);
}

// dual hop 2: zp[r] = sum w*b1h[col]; zn[r] = sum w*b2h[col] (fp32 out)
__global__ void spmm_N2_kernel(float* __restrict__ zp, float* __restrict__ zn) {
    int t = blockIdx.x * blockDim.x + threadIdx.x;
    int r = t >> 4;
    if (r >= NN) return;
    int lane = t & 15;
    int f = lane << 2;
    int j   = g_rowptr1[r];
    int end = g_rowptr1[r + 1];
    float ap[4] = {0.f, 0.f, 0.f, 0.f};
    float an[4] = {0.f, 0.f, 0.f, 0.f};
    for (; j + 2 <= end; j += 2) {
        int2 e0 = g_edges1[j], e1 = g_edges1[j + 1];
        float w0 = __int_as_float(e0.y), w1 = __int_as_float(e1.y);
        uint2 vp0 = g_b1h[(size_t)e0.x * 16 + lane];
        uint2 vn0 = g_b2h[(size_t)e0.x * 16 + lane];
        uint2 vp1 = g_b1h[(size_t)e1.x * 16 + lane];
        uint2 vn1 = g_b2h[(size_t)e1.x * 16 + lane];
        fma4(ap, vp0, w0);
        fma4(an, vn0, w0);
        fma4(ap, vp1, w1);
        fma4(an, vn1, w1);
    }
    if (j < end) {
        int2 e0 = g_edges1[j];
        float w0 = __int_as_float(e0.y);
        uint2 vp0 = g_b1h[(size_t)e0.x * 16 + lane];
        uint2 vn0 = g_b2h[(size_t)e0.x * 16 + lane];
        fma4(ap, vp0, w0);
        fma4(an, vn0, w0);
    }
    *(float4*)(zp + (size_t)r * DD + f) = make_float4(ap[0], ap[1], ap[2], ap[3]);
    *(float4*)(zn + (size_t)r * DD + f) = make_float4(an[0], an[1], an[2], an[3]);
}

extern "C" void kernel_launch(void* const* d_in, const int* in_sizes, int n_in,
                              void* d_out, int out_size) {
    const float* x    = (const float*)d_in[0];
    const int*   shuf = (const int*)  d_in[1];
    const int*   ei   = (const int*)  d_in[2];
    const float* ew   = (const float*)d_in[3];
    const int*   ni   = (const int*)  d_in[4];
    const float* nw   = (const float*)d_in[5];
    const float* temp = (const float*)d_in[6];
    float* out = (float*)d_out;   // [out | z_pos | z_neg]

    const int* erow = ei;
    const int* ecol = ei + EE;
    const int* nrow = ni;
    const int* ncol = ni + EE;

    const int TB = 256;
    const int blkN    = (NN + TB - 1) / TB;
    const int blk2E   = (2 * EE + TB - 1) / TB;
    const int blkHX   = (2 * EE + NH2 + TB - 1) / TB;
    const int blkR16  = (NN * 16 + TB - 1) / TB;
    const int nScanB  = (NN + 1023) / 1024;

    // ---- CSR build (both graphs) + weighted degree + fp16 x ----
    zero_meta_kernel<<<blkN, TB>>>();
    hist2_xh_kernel<<<blkHX, TB>>>(erow, ew, nrow, x);
    scan1_kernel<<<dim3(nScanB, 2), 1024>>>();
    scan2_kernel<<<dim3(1, 2), 128>>>(nScanB);
    scan3_kernel<<<dim3(nScanB, 2), 1024>>>();
    scatter2_kernel<<<blk2E, TB>>>(erow, ecol, ew, nrow, ncol, nw);

    // ---- spectral polynomial ----
    spmm_L1_kernel<<<blkR16, TB>>>(x);
    spmm_L2_kernel<<<blkR16, TB>>>(x, temp, out);

    // ---- z_pos / z_neg ----
    outsh_kernel<<<blkR16, TB>>>(shuf);
    spmm_N1_kernel<<<blkR16, TB>>>();
    spmm_N2_kernel<<<blkR16, TB>>>(out + (size_t)ND, out + 2 * (size_t)ND);
}

// round 5
// speedup vs baseline: 2.3852x; 1.0558x over previous
#include <cuda_runtime.h>
#include <cuda_fp16.h>
#include <cstdint>

#define NN 100000      // nodes
#define DD 64          // feature dim
#define EE 1250000     // edges
#define ND (NN * DD)
#define NH2 (ND / 4)   // uint2 count for fp16 feature arrays (4 halfs per uint2)

// ---------------- scratch (device globals, allocation-free) ----------------
__device__ int   g_cnt0[NN];
__device__ int   g_cnt1[NN];
__device__ float g_degf[NN];
__device__ int   g_rowptr0[NN + 1];
__device__ int   g_rowptr1[NN + 1];
__device__ int   g_cur0[NN];
__device__ int   g_cur1[NN];
__device__ int   g_bsum0[128];
__device__ int   g_bsum1[128];
__device__ int2  g_edges0[EE];   // edge graph sorted by row: {col, w_norm}
__device__ int2  g_edges1[EE];   // nb graph sorted by row:   {col, w}
__device__ float g_dis[NN];
__device__ uint2 g_xh[NH2];      // x fp16
__device__ uint2 g_lxh[NH2];     // Lx fp16
__device__ uint2 g_outh[NH2];    // out fp16
__device__ uint2 g_b1h[NH2];     // N(out) fp16
__device__ uint2 g_b2h[NH2];     // N(out[shuf]) fp16

// ---------------- helpers ----------------
__device__ __forceinline__ void fma4(float* acc, uint2 v, float w) {
    __half2 h0 = *reinterpret_cast<__half2*>(&v.x);
    __half2 h1 = *reinterpret_cast<__half2*>(&v.y);
    float2 f0 = __half22float2(h0);
    float2 f1 = __half22float2(h1);
    acc[0] += w * f0.x;
    acc[1] += w * f0.y;
    acc[2] += w * f1.x;
    acc[3] += w * f1.y;
}

__device__ __forceinline__ float4 unpack4(uint2 v) {
    __half2 h0 = *reinterpret_cast<__half2*>(&v.x);
    __half2 h1 = *reinterpret_cast<__half2*>(&v.y);
    float2 f0 = __half22float2(h0);
    float2 f1 = __half22float2(h1);
    return make_float4(f0.x, f0.y, f1.x, f1.y);
}

__device__ __forceinline__ uint2 pack4(float a, float b, float c, float d) {
    uint2 u;
    __half2 h0 = __floats2half2_rn(a, b);
    __half2 h1 = __floats2half2_rn(c, d);
    u.x = *reinterpret_cast<unsigned*>(&h0);
    u.y = *reinterpret_cast<unsigned*>(&h1);
    return u;
}

// ---------------- CSR build ----------------
__global__ void zero_meta_kernel() {
    int i = blockIdx.x * blockDim.x + threadIdx.x;
    if (i < NN) { g_cnt0[i] = 0; g_cnt1[i] = 0; g_degf[i] = 0.f; }
}

// seg1: edge-graph histogram + weighted degree; seg2: nb histogram; seg3: fp16 x
__global__ void hist2_xh_kernel(const int* __restrict__ er, const float* __restrict__ ew,
                                const int* __restrict__ nr, const float* __restrict__ x) {
    int i = blockIdx.x * blockDim.x + threadIdx.x;
    if (i < EE) {
        int r = er[i];
        atomicAdd(&g_cnt0[r], 1);
        atomicAdd(&g_degf[r], ew[i]);
    } else if (i < 2 * EE) {
        atomicAdd(&g_cnt1[nr[i - EE]], 1);
    } else if (i < 2 * EE + NH2) {
        int k = i - 2 * EE;
        float4 v = *(const float4*)(x + (size_t)k * 4);
        g_xh[k] = pack4(v.x, v.y, v.z, v.w);
    }
}

// scan phase 1 (+ fused dis computation on the g==0 slice)
__global__ void scan1_kernel() {
    __shared__ int sh[1024];
    const int g = blockIdx.y;
    const int* cnt  = g ? g_cnt1    : g_cnt0;
    int*       rptr = g ? g_rowptr1 : g_rowptr0;
    int*       bsum = g ? g_bsum1   : g_bsum0;
    int tid = threadIdx.x;
    int i = blockIdx.x * 1024 + tid;
    if (g == 0 && i < NN) {
        float d = g_degf[i];
        g_dis[i] = (d > 0.f) ? rsqrtf(d) : 0.f;
    }
    int v = (i < NN) ? cnt[i] : 0;
    sh[tid] = v;
    __syncthreads();
    for (int off = 1; off < 1024; off <<= 1) {
        int t = (tid >= off) ? sh[tid - off] : 0;
        __syncthreads();
        sh[tid] += t;
        __syncthreads();
    }
    int incl = sh[tid];
    if (i < NN) rptr[i] = incl - v;
    if (tid == 1023) bsum[blockIdx.x] = incl;
}

// merged scan2+scan3: every block redundantly scans the <=98 block sums,
// adds its offset, writes final rowptr + cursors
__global__ void scan23_kernel(int nblocks) {
    __shared__ int sh[128];
    const int g = blockIdx.y;
    int* rptr = g ? g_rowptr1 : g_rowptr0;
    int* cur  = g ? g_cur1    : g_cur0;
    const int* bsum = g ? g_bsum1 : g_bsum0;
    int tid = threadIdx.x;
    if (tid < 128) {
        sh[tid] = (tid < nblocks) ? bsum[tid] : 0;
    }
    __syncthreads();
    // serial-ish scan over 128 entries by thread 0 (tiny)
    if (tid == 0) {
        int run = 0;
        for (int k = 0; k < 128; k++) {
            int t = sh[k];
            sh[k] = run;
            run += t;
        }
    }
    __syncthreads();
    int off = sh[blockIdx.x];
    int i = blockIdx.x * 1024 + tid;
    if (i < NN) {
        int p = rptr[i] + off;
        rptr[i] = p;
        cur[i]  = p;
    }
    if (i == NN) rptr[NN] = EE;
}

// scatter: graph0 stores {col, w_norm = dis[r]*w*dis[c]}, graph1 stores {col, w}
__global__ void scatter2_kernel(const int* __restrict__ er, const int* __restrict__ ec,
                                const float* __restrict__ ew,
                                const int* __restrict__ nr, const int* __restrict__ nc,
                                const float* __restrict__ nw) {
    int i = blockIdx.x * blockDim.x + threadIdx.x;
    if (i < EE) {
        int r = er[i];
        int c = ec[i];
        float wn = __ldg(&g_dis[r]) * ew[i] * __ldg(&g_dis[c]);
        int p = atomicAdd(&g_cur0[r], 1);
        g_edges0[p] = make_int2(c, __float_as_int(wn));
    } else if (i < 2 * EE) {
        int k = i - EE;
        int p = atomicAdd(&g_cur1[nr[k]], 1);
        g_edges1[p] = make_int2(nc[k], __float_as_int(nw[k]));
    }
}

// ---------------- SPMM kernels: 16 lanes per row, 4 features per lane ----------------

// Lx = x - Anorm x (gathers xh fp16, weights prenormalized); writes lxh fp16
__global__ void spmm_L1_kernel(const float* __restrict__ x) {
    int t = blockIdx.x * blockDim.x + threadIdx.x;
    int r = t >> 4;
    if (r >= NN) return;
    int lane = t & 15;
    int f = lane << 2;
    int j   = g_rowptr0[r];
    int end = g_rowptr0[r + 1];
    float acc[4] = {0.f, 0.f, 0.f, 0.f};
    for (; j + 2 <= end; j += 2) {
        int2 e0 = g_edges0[j], e1 = g_edges0[j + 1];
        uint2 v0 = g_xh[(size_t)e0.x * 16 + lane];
        uint2 v1 = g_xh[(size_t)e1.x * 16 + lane];
        fma4(acc, v0, __int_as_float(e0.y));
        fma4(acc, v1, __int_as_float(e1.y));
    }
    if (j < end) {
        int2 e0 = g_edges0[j];
        uint2 v0 = g_xh[(size_t)e0.x * 16 + lane];
        fma4(acc, v0, __int_as_float(e0.y));
    }
    float4 xv = *(const float4*)(x + (size_t)r * DD + f);
    g_lxh[(size_t)r * 16 + lane] =
        pack4(xv.x - acc[0], xv.y - acc[1], xv.z - acc[2], xv.w - acc[3]);
}

// out = c0*x + c1*Lx + c2*(Lx - Anorm*Lx); writes out fp32 + outh fp16
__global__ void spmm_L2_kernel(const float* __restrict__ x,
                               const float* __restrict__ temp,
                               float* __restrict__ out) {
    int t = blockIdx.x * blockDim.x + threadIdx.x;
    int r = t >> 4;
    if (r >= NN) return;
    int lane = t & 15;
    int f = lane << 2;
    int j   = g_rowptr0[r];
    int end = g_rowptr0[r + 1];
    float acc[4] = {0.f, 0.f, 0.f, 0.f};
    for (; j + 2 <= end; j += 2) {
        int2 e0 = g_edges0[j], e1 = g_edges0[j + 1];
        uint2 v0 = g_lxh[(size_t)e0.x * 16 + lane];
        uint2 v1 = g_lxh[(size_t)e1.x * 16 + lane];
        fma4(acc, v0, __int_as_float(e0.y));
        fma4(acc, v1, __int_as_float(e1.y));
    }
    if (j < end) {
        int2 e0 = g_edges0[j];
        uint2 v0 = g_lxh[(size_t)e0.x * 16 + lane];
        fma4(acc, v0, __int_as_float(e0.y));
    }
    float t0 = fmaxf(__ldg(temp + 0), 0.f);
    float t1 = fmaxf(__ldg(temp + 1), 0.f);
    float t2 = fmaxf(__ldg(temp + 2), 0.f);
    float c0 = t0;
    float c1 = t1 - t0;
    float c2 = (t0 + t2 - 2.f * t1) * 0.25f;
    float4 xv = *(const float4*)(x + (size_t)r * DD + f);
    float4 lv = unpack4(g_lxh[(size_t)r * 16 + lane]);
    float o0 = c0 * xv.x + c1 * lv.x + c2 * (lv.x - acc[0]);
    float o1 = c0 * xv.y + c1 * lv.y + c2 * (lv.y - acc[1]);
    float o2 = c0 * xv.z + c1 * lv.z + c2 * (lv.z - acc[2]);
    float o3 = c0 * xv.w + c1 * lv.w + c2 * (lv.w - acc[3]);
    *(float4*)(out + (size_t)r * DD + f) = make_float4(o0, o1, o2, o3);
    g_outh[(size_t)r * 16 + lane] = pack4(o0, o1, o2, o3);
}

// dual hop 1: b1h[r] = sum w*outh[col]; b2h[r] = sum w*outh[shuf[col]]
__global__ void spmm_N1_kernel(const int* __restrict__ shuf) {
    int t = blockIdx.x * blockDim.x + threadIdx.x;
    int r = t >> 4;
    if (r >= NN) return;
    int lane = t & 15;
    int j   = g_rowptr1[r];
    int end = g_rowptr1[r + 1];
    float ap[4] = {0.f, 0.f, 0.f, 0.f};
    float an[4] = {0.f, 0.f, 0.f, 0.f};
    for (; j + 2 <= end; j += 2) {
        int2 e0 = g_edges1[j], e1 = g_edges1[j + 1];
        int c0 = e0.x, c1 = e1.x;
        int s0 = __ldg(shuf + c0);
        int s1 = __ldg(shuf + c1);
        float w0 = __int_as_float(e0.y), w1 = __int_as_float(e1.y);
        uint2 vp0 = g_outh[(size_t)c0 * 16 + lane];
        uint2 vp1 = g_outh[(size_t)c1 * 16 + lane];
        uint2 vn0 = g_outh[(size_t)s0 * 16 + lane];
        uint2 vn1 = g_outh[(size_t)s1 * 16 + lane];
        fma4(ap, vp0, w0);
        fma4(ap, vp1, w1);
        fma4(an, vn0, w0);
        fma4(an, vn1, w1);
    }
    if (j < end) {
        int2 e0 = g_edges1[j];
        int c0 = e0.x;
        int s0 = __ldg(shuf + c0);
        float w0 = __int_as_float(e0.y);
        uint2 vp0 = g_outh[(size_t)c0 * 16 + lane];
        uint2 vn0 = g_outh[(size_t)s0 * 16 + lane];
        fma4(ap, vp0, w0);
        fma4(an, vn0, w0);
    }
    g_b1h[(size_t)r * 16 + lane] = pack4(ap[0], ap[1], ap[2], ap[3]);
    g_b2h[(size_t)r * 16 + lane] = pack4(an[0], an[1], an[2], an[3]);
}

// dual hop 2: zp[r] = sum w*b1h[col]; zn[r] = sum w*b2h[col] (fp32 out)
__global__ void spmm_N2_kernel(float* __restrict__ zp, float* __restrict__ zn) {
    int t = blockIdx.x * blockDim.x + threadIdx.x;
    int r = t >> 4;
    if (r >= NN) return;
    int lane = t & 15;
    int f = lane << 2;
    int j   = g_rowptr1[r];
    int end = g_rowptr1[r + 1];
    float ap[4] = {0.f, 0.f, 0.f, 0.f};
    float an[4] = {0.f, 0.f, 0.f, 0.f};
    for (; j + 2 <= end; j += 2) {
        int2 e0 = g_edges1[j], e1 = g_edges1[j + 1];
        float w0 = __int_as_float(e0.y), w1 = __int_as_float(e1.y);
        uint2 vp0 = g_b1h[(size_t)e0.x * 16 + lane];
        uint2 vn0 = g_b2h[(size_t)e0.x * 16 + lane];
        uint2 vp1 = g_b1h[(size_t)e1.x * 16 + lane];
        uint2 vn1 = g_b2h[(size_t)e1.x * 16 + lane];
        fma4(ap, vp0, w0);
        fma4(an, vn0, w0);
        fma4(ap, vp1, w1);
        fma4(an, vn1, w1);
    }
    if (j < end) {
        int2 e0 = g_edges1[j];
        float w0 = __int_as_float(e0.y);
        uint2 vp0 = g_b1h[(size_t)e0.x * 16 + lane];
        uint2 vn0 = g_b2h[(size_t)e0.x * 16 + lane];
        fma4(ap, vp0, w0);
        fma4(an, vn0, w0);
    }
    *(float4*)(zp + (size_t)r * DD + f) = make_float4(ap[0], ap[1], ap[2], ap[3]);
    *(float4*)(zn + (size_t)r * DD + f) = make_float4(an[0], an[1], an[2], an[3]);
}

extern "C" void kernel_launch(void* const* d_in, const int* in_sizes, int n_in,
                              void* d_out, int out_size) {
    const float* x    = (const float*)d_in[0];
    const int*   shuf = (const int*)  d_in[1];
    const int*   ei   = (const int*)  d_in[2];
    const float* ew   = (const float*)d_in[3];
    const int*   ni   = (const int*)  d_in[4];
    const float* nw   = (const float*)d_in[5];
    const float* temp = (const float*)d_in[6];
    float* out = (float*)d_out;   // [out | z_pos | z_neg]

    const int* erow = ei;
    const int* ecol = ei + EE;
    const int* nrow = ni;
    const int* ncol = ni + EE;

    const int TB = 256;
    const int blkN    = (NN + TB - 1) / TB;
    const int blk2E   = (2 * EE + TB - 1) / TB;
    const int blkHX   = (2 * EE + NH2 + TB - 1) / TB;
    const int blkR16  = (NN * 16 + TB - 1) / TB;
    const int nScanB  = (NN + 1023) / 1024;

    // ---- CSR build (both graphs) + weighted degree + fp16 x ----
    zero_meta_kernel<<<blkN, TB>>>();
    hist2_xh_kernel<<<blkHX, TB>>>(erow, ew, nrow, x);
    scan1_kernel<<<dim3(nScanB, 2), 1024>>>();
    scan23_kernel<<<dim3(nScanB, 2), 1024>>>(nScanB);
    scatter2_kernel<<<blk2E, TB>>>(erow, ecol, ew, nrow, ncol, nw);

    // ---- spectral polynomial ----
    spmm_L1_kernel<<<blkR16, TB>>>(x);
    spmm_L2_kernel<<<blkR16, TB>>>(x, temp, out);

    // ---- z_pos / z_neg ----
    spmm_N1_kernel<<<blkR16, TB>>>(shuf);
    spmm_N2_kernel<<<blkR16, TB>>>(out + (size_t)ND, out + 2 * (size_t)ND);
}